// round 3
// baseline (speedup 1.0000x reference)
#include <cuda_runtime.h>
#include <cuda_fp16.h>
#include <math.h>

#define TPB 512
#define CNT 8192              // points per group (power of 2)
#define SPG 8192              // pairs per group
#define NF4 (CNT * 9 / 4)     // 18432 float4 per group slab
#define SMEM_BYTES (12 * CNT) // 96 KB: (half2 xy + half z) x 2 arrays

__device__ double g_acc = 0.0;
__device__ unsigned int g_count = 0;

__device__ __forceinline__ void stage_slab(const float4* __restrict__ src,
                                           __half* __restrict__ s_xy,
                                           __half* __restrict__ s_z)
{
    // Coalesced float4 stream over the group's [CNT,3,3] slab; keep row 1 (comps 3,4,5).
    for (int i = threadIdx.x; i < NF4; i += TPB) {
        float4 v = src[i];
        int f0 = i * 4;
        int p = f0 / 9;
        int c = f0 - p * 9;
        float vals[4] = {v.x, v.y, v.z, v.w};
        #pragma unroll
        for (int k = 0; k < 4; k++) {
            if (c == 3)      s_xy[2 * p]     = __float2half(vals[k]);
            else if (c == 4) s_xy[2 * p + 1] = __float2half(vals[k]);
            else if (c == 5) s_z[p]          = __float2half(vals[k]);
            if (++c == 9) { c = 0; ++p; }
        }
    }
}

__device__ __forceinline__ float pair_term(int l, int r,
                                           const __half* __restrict__ sxy_i,
                                           const __half* __restrict__ sz_i,
                                           const __half* __restrict__ sxy_t,
                                           const __half* __restrict__ sz_t)
{
    float2 a = __half22float2(*(const __half2*)(sxy_i + 2 * l));
    float2 b = __half22float2(*(const __half2*)(sxy_i + 2 * r));
    float az = __half2float(sz_i[l]);
    float bz = __half2float(sz_i[r]);

    float2 c = __half22float2(*(const __half2*)(sxy_t + 2 * l));
    float2 d = __half22float2(*(const __half2*)(sxy_t + 2 * r));
    float cz = __half2float(sz_t[l]);
    float dz = __half2float(sz_t[r]);

    float ux = a.x - b.x, uy = a.y - b.y, uz = az - bz;
    float d_in = sqrtf(fmaf(ux, ux, fmaf(uy, uy, uz * uz)));

    float vx = c.x - d.x, vy = c.y - d.y, vz = cz - dz;
    float d_tg = sqrtf(fmaf(vx, vx, fmaf(vy, vy, vz * vz)));

    float t = d_in - d_tg;
    return t * t;
}

__global__ void __launch_bounds__(TPB, 2)
rgn_group_kernel(const float* __restrict__ inputs,
                 const float* __restrict__ target,
                 const int* __restrict__ left,
                 const int* __restrict__ right,
                 float* __restrict__ out,
                 int npairs)
{
    extern __shared__ unsigned char smem_raw[];
    __half* s_xy_in = (__half*)(smem_raw);             // CNT half2 = 32KB
    __half* s_z_in  = (__half*)(smem_raw + 4 * CNT);   // CNT half  = 16KB
    __half* s_xy_tg = (__half*)(smem_raw + 6 * CNT);   // 32KB
    __half* s_z_tg  = (__half*)(smem_raw + 10 * CNT);  // 16KB

    const int g = blockIdx.x;
    const size_t slab = (size_t)g * CNT * 9;

    stage_slab((const float4*)(inputs + slab), s_xy_in, s_z_in);
    stage_slab((const float4*)(target + slab), s_xy_tg, s_z_tg);
    __syncthreads();

    const int2* Lp = (const int2*)(left  + (size_t)g * SPG);
    const int2* Rp = (const int2*)(right + (size_t)g * SPG);

    float acc = 0.0f;
    #pragma unroll 4
    for (int i = threadIdx.x; i < SPG / 2; i += TPB) {
        int2 L = Lp[i];
        int2 R = Rp[i];
        acc += pair_term(L.x & (CNT - 1), R.x & (CNT - 1), s_xy_in, s_z_in, s_xy_tg, s_z_tg);
        acc += pair_term(L.y & (CNT - 1), R.y & (CNT - 1), s_xy_in, s_z_in, s_xy_tg, s_z_tg);
    }

    // block reduce
    #pragma unroll
    for (int off = 16; off > 0; off >>= 1)
        acc += __shfl_down_sync(0xFFFFFFFFu, acc, off);

    __shared__ float warp_sums[TPB / 32];
    const int lane = threadIdx.x & 31;
    const int wid  = threadIdx.x >> 5;
    if (lane == 0) warp_sums[wid] = acc;
    __syncthreads();

    if (wid == 0) {
        float s = (lane < TPB / 32) ? warp_sums[lane] : 0.0f;
        #pragma unroll
        for (int off = (TPB / 64); off > 0; off >>= 1)
            s += __shfl_down_sync(0xFFFFFFFFu, s, off);

        if (lane == 0) {
            atomicAdd(&g_acc, (double)s);
            __threadfence();
            unsigned int done = atomicAdd(&g_count, 1u);
            if (done == gridDim.x - 1) {
                out[0] = (float)(g_acc / (double)npairs);
                g_acc = 0.0;   // reset for next graph replay
                g_count = 0;
            }
        }
    }
}

extern "C" void kernel_launch(void* const* d_in, const int* in_sizes, int n_in,
                              void* d_out, int out_size) {
    const float* inputs = (const float*)d_in[0];
    const float* target = (const float*)d_in[1];
    const int*   left   = (const int*)d_in[2];
    const int*   right  = (const int*)d_in[3];
    float* out = (float*)d_out;

    int npairs = in_sizes[2];
    int groups = npairs / SPG;   // 512

    cudaFuncSetAttribute(rgn_group_kernel,
                         cudaFuncAttributeMaxDynamicSharedMemorySize, SMEM_BYTES);

    rgn_group_kernel<<<groups, TPB, SMEM_BYTES>>>(inputs, target, left, right, out, npairs);
}

// round 4
// speedup vs baseline: 3.0806x; 3.0806x over previous
#include <cuda_runtime.h>
#include <cuda_fp16.h>
#include <math.h>

#define TPB 512
#define CNT 8192              // points per group
#define SPG 8192              // pairs per group
#define PPT_POINTS (CNT / TPB)   // 16 points per thread per array
#define SMEM_BYTES (12 * CNT)    // 96 KB: (half2 xy + half z) x 2 arrays

__device__ double g_acc = 0.0;
__device__ unsigned int g_count = 0;

// Stage CA rows (floats p*9+3..5) of one group slab into fp16 planes.
// 3 scalar LDG.32 per point, zero demux ALU, k-loop unrolled for MLP.
__device__ __forceinline__ void stage_slab(const float* __restrict__ src,
                                           __half2* __restrict__ s_xy,
                                           __half*  __restrict__ s_z)
{
    #pragma unroll
    for (int k = 0; k < PPT_POINTS; k++) {
        const int p = threadIdx.x + k * TPB;
        const float* row = src + (size_t)p * 9 + 3;
        float x = __ldg(row + 0);
        float y = __ldg(row + 1);
        float z = __ldg(row + 2);
        s_xy[p] = __floats2half2_rn(x, y);
        s_z[p]  = __float2half_rn(z);
    }
}

__device__ __forceinline__ float pair_term(int l, int r,
                                           const __half2* __restrict__ sxy_i,
                                           const __half*  __restrict__ sz_i,
                                           const __half2* __restrict__ sxy_t,
                                           const __half*  __restrict__ sz_t)
{
    float2 a = __half22float2(sxy_i[l]);
    float2 b = __half22float2(sxy_i[r]);
    float az = __half2float(sz_i[l]);
    float bz = __half2float(sz_i[r]);

    float2 c = __half22float2(sxy_t[l]);
    float2 d = __half22float2(sxy_t[r]);
    float cz = __half2float(sz_t[l]);
    float dz = __half2float(sz_t[r]);

    float ux = a.x - b.x, uy = a.y - b.y, uz = az - bz;
    float d_in = sqrtf(fmaf(ux, ux, fmaf(uy, uy, uz * uz)));

    float vx = c.x - d.x, vy = c.y - d.y, vz = cz - dz;
    float d_tg = sqrtf(fmaf(vx, vx, fmaf(vy, vy, vz * vz)));

    float t = d_in - d_tg;
    return t * t;
}

__global__ void __launch_bounds__(TPB, 2)
rgn_group_kernel(const float* __restrict__ inputs,
                 const float* __restrict__ target,
                 const int* __restrict__ left,
                 const int* __restrict__ right,
                 float* __restrict__ out,
                 int npairs)
{
    extern __shared__ unsigned char smem_raw[];
    __half2* s_xy_in = (__half2*)(smem_raw);             // 32 KB
    __half*  s_z_in  = (__half*)(smem_raw + 4 * CNT);    // 16 KB
    __half2* s_xy_tg = (__half2*)(smem_raw + 6 * CNT);   // 32 KB
    __half*  s_z_tg  = (__half*)(smem_raw + 10 * CNT);   // 16 KB

    const int g = blockIdx.x;
    const size_t slab = (size_t)g * CNT * 9;

    stage_slab(inputs + slab, s_xy_in, s_z_in);
    stage_slab(target + slab, s_xy_tg, s_z_tg);
    __syncthreads();

    const int2* Lp = (const int2*)(left  + (size_t)g * SPG);
    const int2* Rp = (const int2*)(right + (size_t)g * SPG);

    float acc = 0.0f;
    #pragma unroll 4
    for (int i = threadIdx.x; i < SPG / 2; i += TPB) {
        int2 L = Lp[i];
        int2 R = Rp[i];
        acc += pair_term(L.x & (CNT - 1), R.x & (CNT - 1), s_xy_in, s_z_in, s_xy_tg, s_z_tg);
        acc += pair_term(L.y & (CNT - 1), R.y & (CNT - 1), s_xy_in, s_z_in, s_xy_tg, s_z_tg);
    }

    // block reduce
    #pragma unroll
    for (int off = 16; off > 0; off >>= 1)
        acc += __shfl_down_sync(0xFFFFFFFFu, acc, off);

    __shared__ float warp_sums[TPB / 32];
    const int lane = threadIdx.x & 31;
    const int wid  = threadIdx.x >> 5;
    if (lane == 0) warp_sums[wid] = acc;
    __syncthreads();

    if (wid == 0) {
        float s = (lane < TPB / 32) ? warp_sums[lane] : 0.0f;
        #pragma unroll
        for (int off = (TPB / 64); off > 0; off >>= 1)
            s += __shfl_down_sync(0xFFFFFFFFu, s, off);

        if (lane == 0) {
            atomicAdd(&g_acc, (double)s);
            __threadfence();
            unsigned int done = atomicAdd(&g_count, 1u);
            if (done == gridDim.x - 1) {
                out[0] = (float)(g_acc / (double)npairs);
                g_acc = 0.0;   // reset for next graph replay
                g_count = 0;
            }
        }
    }
}

extern "C" void kernel_launch(void* const* d_in, const int* in_sizes, int n_in,
                              void* d_out, int out_size) {
    const float* inputs = (const float*)d_in[0];
    const float* target = (const float*)d_in[1];
    const int*   left   = (const int*)d_in[2];
    const int*   right  = (const int*)d_in[3];
    float* out = (float*)d_out;

    int npairs = in_sizes[2];
    int groups = npairs / SPG;   // 512

    cudaFuncSetAttribute(rgn_group_kernel,
                         cudaFuncAttributeMaxDynamicSharedMemorySize, SMEM_BYTES);

    rgn_group_kernel<<<groups, TPB, SMEM_BYTES>>>(inputs, target, left, right, out, npairs);
}